// round 3
// baseline (speedup 1.0000x reference)
#include <cuda_runtime.h>
#include <cfloat>
#include <math.h>

// Edge lists for the two MSTs (max n = 4096 -> 4095 edges each).
#define NMAX 4096
__device__ int2 g_edges[2][NMAX];

// One block per matrix. 1024 threads; thread t owns indices 4t..4t+3 in
// registers. min_dist == FLT_MAX is the "in tree" sentinel — identical to the
// reference's jnp.where(in_tree, finfo.max, min_dist) masking. Argmin
// tie-breaks to the lowest index (matches jnp.argmin) via packed u64 keys.
__global__ __launch_bounds__(1024, 1)
void mst_kernel(const float* __restrict__ d1,
                const float* __restrict__ d2,
                int n)
{
    const float* __restrict__ d = (blockIdx.x == 0) ? d1 : d2;
    int2* edges = g_edges[blockIdx.x];

    const int tid  = threadIdx.x;
    const int lane = tid & 31;
    const int wid  = tid >> 5;
    const int base = tid << 2;            // first of 4 owned indices

    __shared__ unsigned long long warp_best[32];
    __shared__ unsigned long long sel_key;

    // ---- init: min_dist = d[0,:], parent = 0, node 0 in tree ----
    float md[4];
    int   par[4];
    float4 r0 = reinterpret_cast<const float4*>(d)[tid];
    md[0] = r0.x; md[1] = r0.y; md[2] = r0.z; md[3] = r0.w;
    par[0] = par[1] = par[2] = par[3] = 0;
    if (tid == 0) md[0] = FLT_MAX;        // node 0 already in tree

    for (int it = 0; it < n - 1; ++it) {
        // ---- local argmin over owned 4 (key = float_bits<<20 | idx) ----
        // float bit pattern is order-preserving for non-negative values;
        // min() on the packed key -> lowest value, then lowest index.
        unsigned long long best = 0xFFFFFFFFFFFFFFFFull;
        #pragma unroll
        for (int k = 0; k < 4; ++k) {
            unsigned long long key =
                (((unsigned long long)__float_as_uint(md[k])) << 20)
                | (unsigned)(base + k);
            best = min(best, key);
        }
        // ---- warp reduction ----
        #pragma unroll
        for (int o = 16; o; o >>= 1)
            best = min(best, __shfl_xor_sync(0xffffffffu, best, o));
        if (lane == 0) warp_best[wid] = best;
        __syncthreads();
        // ---- block reduction by warp 0 ----
        if (wid == 0) {
            unsigned long long b = warp_best[lane];
            #pragma unroll
            for (int o = 16; o; o >>= 1)
                b = min(b, __shfl_xor_sync(0xffffffffu, b, o));
            if (lane == 0) sel_key = b;
        }
        __syncthreads();

        const int j = (int)(sel_key & 0xFFFFFu);

        // ---- issue the row load ASAP (the long pole: one DRAM round trip) ----
        const float4 rv =
            reinterpret_cast<const float4*>(d + (size_t)j * n)[tid];

        // ---- owning thread records the edge (parent BEFORE relax) and
        //      marks j in-tree ----
        if ((j >> 2) == tid) {
            edges[it] = make_int2(par[j & 3], j);
            md[j & 3] = FLT_MAX;
        }

        // ---- relax: strictly-less update, skip in-tree (== reference
        //      (dj < min_dist) & ~in_tree with in_tree[j] already set) ----
        float v[4] = { rv.x, rv.y, rv.z, rv.w };
        #pragma unroll
        for (int k = 0; k < 4; ++k) {
            if (md[k] != FLT_MAX && v[k] < md[k]) {
                md[k]  = v[k];
                par[k] = j;
            }
        }
    }
}

// Gather both signatures and reduce:
//   result = sum_{e in p1}(d1[e]-d2[e])^2 + sum_{e in p2}(d1[e]-d2[e])^2
__global__ __launch_bounds__(1024, 1)
void finalize_kernel(const float* __restrict__ d1,
                     const float* __restrict__ d2,
                     float* __restrict__ out,
                     int n)
{
    __shared__ float warp_sums[32];
    const int tid = threadIdx.x;

    float acc = 0.0f;
    for (int i = tid; i < n - 1; i += blockDim.x) {
        int2 e1 = g_edges[0][i];
        int2 e2 = g_edges[1][i];
        size_t o1 = (size_t)e1.x * n + e1.y;
        size_t o2 = (size_t)e2.x * n + e2.y;
        float a = d1[o1] - d2[o1];
        float b = d1[o2] - d2[o2];
        acc += a * a + b * b;
    }
    #pragma unroll
    for (int o = 16; o; o >>= 1)
        acc += __shfl_xor_sync(0xffffffffu, acc, o);
    if ((tid & 31) == 0) warp_sums[tid >> 5] = acc;
    __syncthreads();
    if (tid < 32) {
        float v = (tid < (int)(blockDim.x >> 5)) ? warp_sums[tid] : 0.0f;
        #pragma unroll
        for (int o = 16; o; o >>= 1)
            v += __shfl_xor_sync(0xffffffffu, v, o);
        if (tid == 0) out[0] = v;
    }
}

extern "C" void kernel_launch(void* const* d_in, const int* in_sizes, int n_in,
                              void* d_out, int out_size)
{
    const float* d1 = (const float*)d_in[0];
    const float* d2 = (const float*)d_in[1];
    float* out = (float*)d_out;

    const int n = (int)lrint(sqrt((double)in_sizes[0]));   // 4096

    mst_kernel<<<2, 1024>>>(d1, d2, n);
    finalize_kernel<<<1, 1024>>>(d1, d2, out, n);
}